// round 2
// baseline (speedup 1.0000x reference)
#include <cuda_runtime.h>

// GCN_33560874451187 — scalarized 2-layer GCN.
// N=500000 nodes, E=16000000 edges (int32 indices — JAX x64 disabled).
// All per-node state is scalar: the [1,10]x[10,1] MLP collapses to a
// 10-term scalar nonlinearity between two normalized scatter-adds.

#define N_NODES 500000
#define N_EDGES 16000000

__device__ int   g_deg[N_NODES];
__device__ float g_dinv[N_NODES];
__device__ float g_val[N_NODES];   // y (layer1) then z (layer2)
__device__ float g_acc[N_NODES];   // accumulator, reused both layers

// ---------------------------------------------------------------------------

__global__ void k_zero_deg(int n) {
    int i = blockIdx.x * blockDim.x + threadIdx.x;
    if (i < n) g_deg[i] = 0;
}

// In-degree count: read only the col half of edge_index (int32), 4/thread.
__global__ void k_deg(const int* __restrict__ col, int e4) {
    int i = blockIdx.x * blockDim.x + threadIdx.x;
    if (i < e4) {
        int4 c = ((const int4*)col)[i];
        atomicAdd(&g_deg[c.x], 1);
        atomicAdd(&g_deg[c.y], 1);
        atomicAdd(&g_deg[c.z], 1);
        atomicAdd(&g_deg[c.w], 1);
    }
}

// dinv = rsqrt(deg+1); y = dinv*x; acc starts with self-loop term y[v].
__global__ void k_phase1(const float* __restrict__ x, int n) {
    int i = blockIdx.x * blockDim.x + threadIdx.x;
    if (i < n) {
        float dinv = rsqrtf((float)(g_deg[i] + 1));
        g_dinv[i] = dinv;
        float y = dinv * x[i];
        g_val[i] = y;
        g_acc[i] = y;
    }
}

// Edge sweep: acc[col] += val[row]. Gather table (2MB) is L2-resident.
__global__ void k_agg(const int* __restrict__ row,
                      const int* __restrict__ col, int e4) {
    int i = blockIdx.x * blockDim.x + threadIdx.x;
    if (i < e4) {
        int4 r = ((const int4*)row)[i];
        int4 c = ((const int4*)col)[i];
        float vx = __ldg(&g_val[r.x]);
        float vy = __ldg(&g_val[r.y]);
        float vz = __ldg(&g_val[r.z]);
        float vw = __ldg(&g_val[r.w]);
        atomicAdd(&g_acc[c.x], vx);
        atomicAdd(&g_acc[c.y], vy);
        atomicAdd(&g_acc[c.z], vz);
        atomicAdd(&g_acc[c.w], vw);
    }
}

// s1 = dinv*acc; t = sum_k relu(s1*W1[k]+b1[k])*W2[k]; z = dinv*t;
// reset acc to the layer-2 self-loop term z[v].
__global__ void k_phase2(const float* __restrict__ W1,
                         const float* __restrict__ b1,
                         const float* __restrict__ W2, int n) {
    int i = blockIdx.x * blockDim.x + threadIdx.x;
    if (i < n) {
        float dinv = g_dinv[i];
        float s1 = dinv * g_acc[i];
        float t = 0.0f;
        #pragma unroll
        for (int k = 0; k < 10; k++) {
            float h = fmaf(s1, __ldg(&W1[k]), __ldg(&b1[k]));
            t = fmaf(fmaxf(h, 0.0f), __ldg(&W2[k]), t);
        }
        float z = dinv * t;
        g_val[i] = z;
        g_acc[i] = z;
    }
}

__global__ void k_out(float* __restrict__ out, const float* __restrict__ b2, int n) {
    int i = blockIdx.x * blockDim.x + threadIdx.x;
    if (i < n) {
        float v = fmaf(g_dinv[i], g_acc[i], __ldg(&b2[0]));
        out[i] = fminf(fmaxf(v, -0.5f), 9.5f);
    }
}

// ---------------------------------------------------------------------------

extern "C" void kernel_launch(void* const* d_in, const int* in_sizes, int n_in,
                              void* d_out, int out_size) {
    const float* x   = (const float*)d_in[0];
    const int*   ei  = (const int*)d_in[1];   // int32: JAX x64 disabled
    const float* W1  = (const float*)d_in[2];
    const float* b1  = (const float*)d_in[3];
    const float* W2  = (const float*)d_in[4];
    const float* b2  = (const float*)d_in[5];
    float*       out = (float*)d_out;

    int n = in_sizes[0];            // 500000
    int e = in_sizes[1] / 2;        // 16000000
    if (n > N_NODES) n = N_NODES;
    if (e > N_EDGES) e = N_EDGES;
    int e4 = e / 4;                 // E divisible by 4

    const int* row = ei;
    const int* col = ei + e;

    const int T = 256;
    int nb_n  = (n + T - 1) / T;
    int nb_e4 = (e4 + T - 1) / T;

    k_zero_deg<<<nb_n, T>>>(n);
    k_deg<<<nb_e4, T>>>(col, e4);
    k_phase1<<<nb_n, T>>>(x, n);
    k_agg<<<nb_e4, T>>>(row, col, e4);
    k_phase2<<<nb_n, T>>>(W1, b1, W2, n);
    k_agg<<<nb_e4, T>>>(row, col, e4);
    k_out<<<nb_n, T>>>(out, b2, n);
}